// round 10
// baseline (speedup 1.0000x reference)
#include <cuda_runtime.h>

#define N_ANCH 5000
#define N_CLS 80
#define WORDS 157
#define WSTRIDE 160
#define MAXB 300
#define SCORE_THR_F 0.05f
#define OUT_COLS 84
#define NBUCK 4096
#define KEYCAP 5120
#define CLS_T_STRIDE 5120
#define NTILES ((WORDS * (WORDS + 1)) / 2)
#define A_BLOCKS ((NTILES * 32 + 255) / 256)        // 1551
#define T_BLOCKS ((N_ANCH * N_CLS + 255) / 256)     // 1563
#define SCAN_T 256

__device__ unsigned int g_mask[N_ANCH * WSTRIDE];
__device__ unsigned int g_kept[N_CLS * WSTRIDE];
__device__ float        g_clsT[N_CLS * CLS_T_STRIDE];
__device__ unsigned int g_list[N_CLS * KEYCAP];
__device__ int          g_cnt[N_CLS];

// ---------------------------------------------------------------------------
// 32x32 warp bit transpose
// ---------------------------------------------------------------------------
__device__ __forceinline__ unsigned bit_transpose32(unsigned x, int lane) {
    const unsigned lom[5] = {0x0000FFFFu, 0x00FF00FFu, 0x0F0F0F0Fu, 0x33333333u, 0x55555555u};
    const int      shs[5] = {16, 8, 4, 2, 1};
#pragma unroll
    for (int s = 0; s < 5; ++s) {
        unsigned y = __shfl_xor_sync(0xffffffffu, x, shs[s]);
        unsigned lo = lom[s];
        if ((lane & shs[s]) == 0) x = (x & lo)  | ((y & lo)  << shs[s]);
        else                      x = (x & ~lo) | ((y & ~lo) >> shs[s]);
    }
    return x;
}

// ---------------------------------------------------------------------------
// Kernel P (fused): blocks [0, A_BLOCKS) do IoU tiles; rest transpose cls.
// ---------------------------------------------------------------------------
__global__ void __launch_bounds__(256)
prep_kernel(const float4* __restrict__ boxes, const float* __restrict__ cls) {
    __shared__ float4 sbox[8][32];
    __shared__ float  sarea[8][32];

    if (blockIdx.x >= A_BLOCKS) {
        int t = (blockIdx.x - A_BLOCKS) * 256 + threadIdx.x;
        if (t < N_ANCH * N_CLS) {
            int i = t / N_CLS, c = t - i * N_CLS;
            g_clsT[c * CLS_T_STRIDE + i] = cls[t];
        }
        return;
    }

    const int gw   = (blockIdx.x * blockDim.x + threadIdx.x) >> 5;
    const int lane = threadIdx.x & 31;
    const int wib  = (threadIdx.x >> 5);
    if (gw >= NTILES) return;

    int J = (int)((sqrtf(8.0f * (float)gw + 1.0f) - 1.0f) * 0.5f);
    while ((J + 1) * (J + 2) / 2 <= gw) ++J;
    while (J * (J + 1) / 2 > gw) --J;
    const int I = gw - J * (J + 1) / 2;

    const int row = (I << 5) + lane;
    const float4 bi = __ldg(&boxes[min(row, N_ANCH - 1)]);
    const float  ai = __fmul_rn(__fsub_rn(bi.z, bi.x), __fsub_rn(bi.w, bi.y));

    const int colL = (J << 5) + lane;
    {
        float4 bc = __ldg(&boxes[min(colL, N_ANCH - 1)]);
        sbox[wib][lane]  = bc;
        sarea[wib][lane] = __fmul_rn(__fsub_rn(bc.z, bc.x), __fsub_rn(bc.w, bc.y));
    }
    __syncwarp(0xffffffffu);

    unsigned word = 0u, fix = 0u;
#pragma unroll
    for (int j = 0; j < 32; ++j) {
        float4 bj = sbox[wib][j];
        float  aj = sarea[wib][j];
        float iw = fmaxf(__fsub_rn(fminf(bi.z, bj.z), fmaxf(bi.x, bj.x)), 0.0f);
        float ih = fmaxf(__fsub_rn(fminf(bi.w, bj.w), fmaxf(bi.y, bj.y)), 0.0f);
        float inter = __fmul_rn(iw, ih);
        float uni   = __fsub_rn(__fadd_rn(ai, aj), inter);
        float diff  = __fmaf_rn(inter, 2.0f, -uni);
        if (diff > 0.0f)                          word |= (1u << j);
        if (fabsf(diff) <= __fmul_rn(uni, 1e-6f)) fix  |= (1u << j);
    }

    if (__any_sync(0xffffffffu, fix != 0u)) {
        while (fix) {
            int j = __ffs(fix) - 1; fix &= fix - 1u;
            float4 bj = sbox[wib][j];
            float  aj = sarea[wib][j];
            float iw = fmaxf(__fsub_rn(fminf(bi.z, bj.z), fmaxf(bi.x, bj.x)), 0.0f);
            float ih = fmaxf(__fsub_rn(fminf(bi.w, bj.w), fmaxf(bi.y, bj.y)), 0.0f);
            float inter = __fmul_rn(iw, ih);
            float uni   = __fsub_rn(__fadd_rn(ai, aj), inter);
            float iou   = __fdiv_rn(inter, fmaxf(uni, 1e-8f));
            if (iou > 0.5f) word |=  (1u << j);
            else            word &= ~(1u << j);
        }
    }

    const unsigned cmaskJ = (J == WORDS - 1) ? 0xFFu : 0xFFFFFFFFu;
    const unsigned cmaskI = (I == WORDS - 1) ? 0xFFu : 0xFFFFFFFFu;
    word &= cmaskJ;

    if (I == J) {
        word &= ~(1u << lane);
        if (row < N_ANCH) g_mask[row * WSTRIDE + J] = word;
    } else {
        unsigned t = bit_transpose32(word, lane) & cmaskI;
        g_mask[row * WSTRIDE + J] = word;
        if (colL < N_ANCH) g_mask[colL * WSTRIDE + I] = t;
    }
}

// ---------------------------------------------------------------------------
// Kernel B1: per-class exact stable descending sort -> g_list / g_cnt
// ---------------------------------------------------------------------------
#define BT 1024

__global__ void __launch_bounds__(BT, 1)
sort_class_kernel() {
    extern __shared__ unsigned char sh_raw[];
    unsigned long long* keys = (unsigned long long*)sh_raw;
    unsigned int* hist   = (unsigned int*)(keys + KEYCAP);
    unsigned int* starts = hist + NBUCK;
    __shared__ unsigned int wsum[32];
    __shared__ int s_cnt;

    const int c = blockIdx.x;
    const int tid = threadIdx.x;
    const int lane = tid & 31;
    const int wid = tid >> 5;
    const float* col = &g_clsT[c * CLS_T_STRIDE];

    for (int b = tid; b < NBUCK; b += BT) hist[b] = 0u;
    __syncthreads();

    for (int i = tid; i < N_ANCH; i += BT) {
        float s = col[i];
        if (s > SCORE_THR_F) {
            int b = min((int)__fmul_rn(s, 4096.0f), NBUCK - 1);
            atomicAdd(&hist[NBUCK - 1 - b], 1u);
        }
    }
    __syncthreads();

    {
        unsigned h0 = hist[tid * 4 + 0], h1 = hist[tid * 4 + 1];
        unsigned h2 = hist[tid * 4 + 2], h3 = hist[tid * 4 + 3];
        unsigned tsum = h0 + h1 + h2 + h3;
        unsigned x = tsum;
#pragma unroll
        for (int o = 1; o < 32; o <<= 1) {
            unsigned y = __shfl_up_sync(0xffffffffu, x, o);
            if (lane >= o) x += y;
        }
        if (lane == 31) wsum[wid] = x;
        __syncthreads();
        if (wid == 0) {
            unsigned v = wsum[lane], xx = v;
#pragma unroll
            for (int o = 1; o < 32; o <<= 1) {
                unsigned y = __shfl_up_sync(0xffffffffu, xx, o);
                if (lane >= o) xx += y;
            }
            wsum[lane] = xx;
            if (lane == 31) s_cnt = (int)xx;
        }
        __syncthreads();
        unsigned te = ((wid > 0) ? wsum[wid - 1] : 0u) + (x - tsum);
        hist[tid * 4 + 0] = te;                  starts[tid * 4 + 0] = te;
        hist[tid * 4 + 1] = te + h0;             starts[tid * 4 + 1] = te + h0;
        hist[tid * 4 + 2] = te + h0 + h1;        starts[tid * 4 + 2] = te + h0 + h1;
        hist[tid * 4 + 3] = te + h0 + h1 + h2;   starts[tid * 4 + 3] = te + h0 + h1 + h2;
    }
    __syncthreads();
    const int cnt = s_cnt;

    for (int i = tid; i < N_ANCH; i += BT) {
        float s = col[i];
        if (s > SCORE_THR_F) {
            int b = min((int)__fmul_rn(s, 4096.0f), NBUCK - 1);
            unsigned pos = atomicAdd(&hist[NBUCK - 1 - b], 1u);
            keys[pos] = ((unsigned long long)__float_as_uint(s) << 32) |
                        (unsigned long long)(0xFFFFFFFFu - (unsigned)i);
        }
    }
    __syncthreads();

    for (int b = tid; b < NBUCK; b += BT) {
        int s0 = (int)starts[b], e0 = (int)hist[b];
        for (int i = s0 + 1; i < e0; ++i) {
            unsigned long long kv = keys[i];
            int j = i - 1;
            while (j >= s0 && keys[j] < kv) { keys[j + 1] = keys[j]; --j; }
            keys[j + 1] = kv;
        }
    }
    __syncthreads();

    if (tid == 0) g_cnt[c] = cnt;
    for (int p = tid; p < cnt; p += BT)
        g_list[c * KEYCAP + p] = 0xFFFFFFFFu - (unsigned)keys[p];
}

// ---------------------------------------------------------------------------
// Kernel B2: pipelined greedy scan.
// Batch k+1 is selected with supp stale-by-one (sound: supp monotone =>
// stale-alive superset of true-alive) and its rows prefetched via cp.async
// into srow[par^1] while batch k resolves from srow[par]. Stale candidates
// are dropped at resolve time by a supp recheck.
// ---------------------------------------------------------------------------
struct ScanShm {
    unsigned slist[KEYCAP];              // 20480 B
    unsigned srow[2][32][WSTRIDE];       // 40960 B
    unsigned supp[WSTRIDE];
    unsigned keptb[WSTRIDE];
    unsigned s_m[8];
    unsigned sbits[32];
    unsigned s_kb;
    int      s_sel;
};

__device__ __forceinline__ void cp_async4(void* smem_dst, const unsigned* gmem_src) {
    unsigned saddr = (unsigned)__cvta_generic_to_shared(smem_dst);
    asm volatile("cp.async.ca.shared.global [%0], [%1], 4;\n"
                 :: "r"(saddr), "l"(gmem_src));
}
__device__ __forceinline__ void cp_commit() {
    asm volatile("cp.async.commit_group;\n");
}
__device__ __forceinline__ void cp_wait1() {
    asm volatile("cp.async.wait_group 1;\n");
}

// Select up to 32 stale-alive candidates from window [cur, cur+256), issue
// cp.async row prefetch into srow[buf]. Advances cur. Returns nf; sets a_l
// (every warp's lane L holds candidate L, R5-style redundant selection).
// Exactly one cp.async group committed per call. Contains one __syncthreads.
__device__ __forceinline__ int select_and_issue(ScanShm* S, int cnt, int& cur,
                                                unsigned& a_l, int w, int lane,
                                                int buf) {
    int pos = cur + threadIdx.x;
    bool ok = (pos < cnt);
    unsigned ca = ok ? S->slist[pos] : 0u;
    bool alive = ok && !((S->supp[ca >> 5] >> (ca & 31)) & 1u);
    unsigned bm = __ballot_sync(0xffffffffu, alive);
    if (lane == 0) S->s_m[w] = bm;
    __syncthreads();

    unsigned mw[8]; int tot = 0;
#pragma unroll
    for (int q = 0; q < 8; ++q) { mw[q] = S->s_m[q]; tot += __popc(mw[q]); }
    int nf = min(tot, 32);
    if (nf == 0) { cur += SCAN_T; a_l = 0u; cp_commit(); return 0; }

    int rem = lane, psel = -1;
#pragma unroll
    for (int q = 0; q < 8; ++q) {
        int cq = __popc(mw[q]);
        if (psel < 0) {
            if (rem < cq) psel = (q << 5) + (int)__fns(mw[q], 0, rem + 1);
            else rem -= cq;
        }
    }
    a_l = (lane < nf) ? S->slist[cur + psel] : 0u;
    int plast = __shfl_sync(0xffffffffu, psel, nf - 1);
    cur += (tot <= 32) ? SCAN_T : (plast + 1);

    // prefetch: warp w handles rows 4w..4w+3, coalesced lane+u*32 pattern
#pragma unroll
    for (int j = 0; j < 4; ++j) {
        int k = (w << 2) + j;
        unsigned ak = __shfl_sync(0xffffffffu, a_l, k);
        if (k < nf) {
#pragma unroll
            for (int u = 0; u < 5; ++u) {
                int wd = lane + (u << 5);
                if (wd < WORDS)
                    cp_async4(&S->srow[buf][k][wd], &g_mask[(size_t)ak * WSTRIDE + wd]);
            }
        }
    }
    cp_commit();
    return nf;
}

__global__ void __launch_bounds__(SCAN_T, 1)
nms_scan_kernel() {
    extern __shared__ unsigned char shraw[];
    ScanShm* S = (ScanShm*)shraw;

    const int c = blockIdx.x;
    const int tid = threadIdx.x;
    const int lane = tid & 31;
    const int w = tid >> 5;
    const int cnt = g_cnt[c];

    for (int i = tid; i < WSTRIDE; i += SCAN_T) { S->supp[i] = 0u; S->keptb[i] = 0u; }
    for (int i = tid; i < cnt; i += SCAN_T) S->slist[i] = __ldg(&g_list[c * KEYCAP + i]);
    __syncthreads();

    int count = 0;
    int cur = 0;
    int par = 0;
    unsigned aC = 0u;
    int nfC = 0;

    // prologue: select + prefetch batch 0 into buffer 0
    if (cur < cnt) nfC = select_and_issue(S, cnt, cur, aC, w, lane, 0);

    while (count < MAXB && (nfC > 0 || cur < cnt)) {
        // select + prefetch NEXT batch into srow[par^1] (supp stale by one batch)
        unsigned aN = 0u; int nfN = 0;
        if (cur < cnt) nfN = select_and_issue(S, cnt, cur, aN, w, lane, par ^ 1);
        else           cp_commit();        // keep group accounting uniform

        cp_wait1();                        // current batch's rows landed
        __syncthreads();                   // S2: srow[par] visible block-wide

        if (nfC > 0) {
            // resolve current batch (warp 0): pairwise from srow[par] + supp recheck
            if (w == 0) {
                unsigned bitsk = 0u; bool aliveNow = false;
                if (lane < nfC) {
                    unsigned aw = aC >> 5, ab = aC & 31u;
                    aliveNow = !((S->supp[aw] >> ab) & 1u);
#pragma unroll
                    for (int m = 0; m < 32; ++m)
                        bitsk |= ((S->srow[par][m][aw] >> ab) & 1u) << m;
                }
                S->sbits[lane] = bitsk;
                unsigned pend0 = __ballot_sync(0xffffffffu, (lane < nfC) && aliveNow);
                __syncwarp(0xffffffffu);
                if (lane == 0) {
                    unsigned kb = 0u; int cl = count; unsigned pend = pend0;
                    while (pend && cl < MAXB) {
                        int f = __ffs(pend) - 1;
                        kb |= 1u << f; ++cl;
                        pend &= ~(1u << f);
                        pend &= ~S->sbits[f];
                    }
                    S->s_kb = kb; S->s_sel = cl;
                }
                __syncwarp(0xffffffffu);
                unsigned kb0 = S->s_kb;
                if (lane < nfC && ((kb0 >> lane) & 1u))
                    atomicOr(&S->keptb[aC >> 5], 1u << (aC & 31u));
            }
            __syncthreads();               // S3: s_kb visible

            unsigned kb = S->s_kb;
            count = S->s_sel;

            // OR kept rows into supp from srow[par] (warp w: rows 4w..4w+3)
            unsigned comb[5] = {0u, 0u, 0u, 0u, 0u};
#pragma unroll
            for (int j = 0; j < 4; ++j) {
                int k = (w << 2) + j;
                if (k < nfC && ((kb >> k) & 1u)) {
#pragma unroll
                    for (int u = 0; u < 5; ++u)
                        comb[u] |= S->srow[par][k][lane + (u << 5)];
                }
            }
#pragma unroll
            for (int u = 0; u < 5; ++u) {
                int wd = lane + (u << 5);
                if (wd < WORDS && comb[u]) atomicOr(&S->supp[wd], comb[u]);
            }
        }
        __syncthreads();                   // S4: supp updated before next ballot

        nfC = nfN; aC = aN; par ^= 1;
    }
    __syncthreads();

    for (int i = tid; i < WSTRIDE; i += SCAN_T)
        g_kept[c * WSTRIDE + i] = S->keptb[i];
}

// ---------------------------------------------------------------------------
// Kernel C: vectorized assemble — one float4 (21 per anchor) per thread
// ---------------------------------------------------------------------------
__global__ void __launch_bounds__(256)
assemble4_kernel(const float4* __restrict__ boxes4,
                 const float4* __restrict__ cls4,
                 float4* __restrict__ out4) {
    int t = blockIdx.x * blockDim.x + threadIdx.x;
    if (t >= N_ANCH * 21) return;
    int i = t / 21;
    int q = t - i * 21;
    float4 v;
    if (q == 0) {
        v = __ldg(&boxes4[i]);
    } else {
        int c0 = (q - 1) * 4;
        v = __ldg(&cls4[(i * N_CLS + c0) >> 2]);
        unsigned wi = (unsigned)i >> 5, bi = (unsigned)i & 31u;
        if (!((g_kept[(c0 + 0) * WSTRIDE + wi] >> bi) & 1u)) v.x = 0.0f;
        if (!((g_kept[(c0 + 1) * WSTRIDE + wi] >> bi) & 1u)) v.y = 0.0f;
        if (!((g_kept[(c0 + 2) * WSTRIDE + wi] >> bi) & 1u)) v.z = 0.0f;
        if (!((g_kept[(c0 + 3) * WSTRIDE + wi] >> bi) & 1u)) v.w = 0.0f;
    }
    out4[t] = v;
}

// ---------------------------------------------------------------------------
extern "C" void kernel_launch(void* const* d_in, const int* in_sizes, int n_in,
                              void* d_out, int out_size) {
    const float* boxes = (const float*)d_in[0];
    const float* cls   = (const float*)d_in[1];
    float* out = (float*)d_out;

    {   // P: fused IoU tiles + transpose
        prep_kernel<<<A_BLOCKS + T_BLOCKS, 256>>>((const float4*)boxes, cls);
    }
    {   // B1: per-class sort
        size_t smem = (size_t)KEYCAP * 8 + (size_t)NBUCK * 4 * 2;
        cudaFuncSetAttribute(sort_class_kernel,
                             cudaFuncAttributeMaxDynamicSharedMemorySize,
                             (int)smem);
        sort_class_kernel<<<N_CLS, BT, smem>>>();
    }
    {   // B2: pipelined greedy scan
        size_t smem = sizeof(ScanShm);
        cudaFuncSetAttribute(nms_scan_kernel,
                             cudaFuncAttributeMaxDynamicSharedMemorySize,
                             (int)smem);
        nms_scan_kernel<<<N_CLS, SCAN_T, smem>>>();
    }
    {   // C: vectorized assemble
        int total = N_ANCH * 21;
        assemble4_kernel<<<(total + 255) / 256, 256>>>(
            (const float4*)boxes, (const float4*)cls, (float4*)out);
    }
}